// round 13
// baseline (speedup 1.0000x reference)
#include <cuda_runtime.h>

#define BATCH 64
#define N     4096
#define NX    128
#define NU    32
#define NY    32
#define L     64
#define NCHUNK (N / L)     // 64
#define MS    (NX * NX)    // 16384

#define Y_ELEMS ((size_t)BATCH * N * NY)

// Scratch (no cudaMalloc allowed)
__device__ float g_PA[6][MS];               // A^2, A^4, A^8, A^16, A^32, A^64
__device__ float g_M[64][NX * NU];          // M[m] = A^m * B   (128x32 each)
__device__ float g_WL[BATCH * NCHUNK * NX]; // chunk-local end contributions
__device__ float g_XS[BATCH * NCHUNK * NX]; // chunk start states x_{cL}
__device__ float g_V[(size_t)BATCH * N * NX]; // V[b][t] = B u_t

// ---------------------------------------------------------------------------
// 128x128 matrix square: out = in * in. grid=128 (row), block=128 (col).
// ---------------------------------------------------------------------------
__global__ void __launch_bounds__(NX) matsq(const float* __restrict__ in,
                                            float* __restrict__ out)
{
    __shared__ float row[NX];
    const int r = blockIdx.x, c = threadIdx.x;
    row[c] = in[r * NX + c];
    __syncthreads();
    float acc = 0.f;
#pragma unroll 16
    for (int j = 0; j < NX; j++) acc += row[j] * in[j * NX + c];
    out[r * NX + c] = acc;
}

// ---------------------------------------------------------------------------
// build_M: ONE launch for all M[m] = A^m B, m = 0..63. grid=64, block=128.
// CTA m chains products over set bits of m (LSB first), matching the fp-op
// order of the old doubling chain exactly.
// ---------------------------------------------------------------------------
__global__ void __launch_bounds__(NX) build_M(
    const float* __restrict__ A,
    const float* __restrict__ B)
{
    __shared__ float cur[NX * NU];   // 16 KB
    const int m = blockIdx.x, r = threadIdx.x;

    for (int idx = r; idx < NX * NU; idx += NX) cur[idx] = B[idx];
    __syncthreads();

    for (int s = 0; s < 6; s++) {
        if ((m >> s) & 1) {
            const float* P = (s == 0) ? A : g_PA[s - 1];
            float a[NX];
            {
                const float4* p4 = (const float4*)(P + (size_t)r * NX);
#pragma unroll
                for (int j = 0; j < NX / 4; j++) {
                    float4 v = p4[j];
                    a[4 * j + 0] = v.x; a[4 * j + 1] = v.y;
                    a[4 * j + 2] = v.z; a[4 * j + 3] = v.w;
                }
            }
            float acc[NU];
#pragma unroll
            for (int v = 0; v < NU; v++) acc[v] = 0.f;
#pragma unroll 4
            for (int j = 0; j < NX; j++) {
                float pj = a[j];
#pragma unroll
                for (int v = 0; v < NU; v++) acc[v] += pj * cur[j * NU + v];
            }
            __syncthreads();
#pragma unroll
            for (int v = 0; v < NU; v++) cur[r * NU + v] = acc[v];
            __syncthreads();
        }
    }

    float* Mo = g_M[m];
    for (int idx = r; idx < NX * NU; idx += NX) Mo[idx] = cur[idx];
}

// ---------------------------------------------------------------------------
// V kernel v2: 2 B-rows per thread -> half the LDS per FMA, STG.64 stores.
// grid=(N/32, BATCH), block=128. h = tid>>6 picks timestep half,
// r2 = tid&63 picks the row pair (2*r2, 2*r2+1).
// ---------------------------------------------------------------------------
__global__ void __launch_bounds__(NX) v_kernel(
    const float* __restrict__ d,
    const float* __restrict__ B,
    float* __restrict__ V)
{
    __shared__ float us[32][NU];     // 4 KB
    const int t0  = blockIdx.x * 32;
    const int b   = blockIdx.y;
    const int tid = threadIdx.x;
    const int h   = tid >> 6;        // 0/1: timestep half
    const int r2  = tid & 63;        // row pair index

    {
        const float4* ug4 = (const float4*)(d + ((size_t)b * N + t0) * NU);
        float4* us4 = (float4*)&us[0][0];
#pragma unroll
        for (int q = 0; q < (32 * NU / 4) / NX; q++)
            us4[tid + NX * q] = ug4[tid + NX * q];
    }
    __syncthreads();

    float ba[NU], bc[NU];
    {
        const float4* b4a = (const float4*)(B + (size_t)(2 * r2) * NU);
        const float4* b4b = (const float4*)(B + (size_t)(2 * r2 + 1) * NU);
#pragma unroll
        for (int q = 0; q < NU / 4; q++) {
            float4 v = b4a[q];
            ba[4 * q + 0] = v.x; ba[4 * q + 1] = v.y;
            ba[4 * q + 2] = v.z; ba[4 * q + 3] = v.w;
            float4 w = b4b[q];
            bc[4 * q + 0] = w.x; bc[4 * q + 1] = w.y;
            bc[4 * q + 2] = w.z; bc[4 * q + 3] = w.w;
        }
    }

    float2* Vb = (float2*)(V + ((size_t)b * N + t0) * NX);
#pragma unroll 4
    for (int t = 0; t < 16; t++) {
        const int tt = h * 16 + t;
        const float4* u4 = (const float4*)us[tt];
        float a0 = 0.f, a1 = 0.f, a2 = 0.f, a3 = 0.f;
        float c0 = 0.f, c1 = 0.f, c2 = 0.f, c3 = 0.f;
#pragma unroll
        for (int q = 0; q < NU / 4; q++) {
            float4 v = u4[q];
            a0 += ba[4 * q + 0] * v.x;  c0 += bc[4 * q + 0] * v.x;
            a1 += ba[4 * q + 1] * v.y;  c1 += bc[4 * q + 1] * v.y;
            a2 += ba[4 * q + 2] * v.z;  c2 += bc[4 * q + 2] * v.z;
            a3 += ba[4 * q + 3] * v.w;  c3 += bc[4 * q + 3] * v.w;
        }
        float2 out;
        out.x = (a0 + a1) + (a2 + a3);
        out.y = (c0 + c1) + (c2 + c3);
        Vb[(size_t)tt * (NX / 2) + r2] = out;
    }
}

// ---------------------------------------------------------------------------
// GEMM for chunk-end contributions (unchanged).
// ---------------------------------------------------------------------------
__global__ void __launch_bounds__(NX) gemm_wl(
    const float* __restrict__ d,
    float* __restrict__ WL)
{
    __shared__ float us[16][128];

    const int c0 = blockIdx.x * 16;
    const int b  = blockIdx.y;
    const int r  = threadIdx.x;

    const float* ub = d + (size_t)b * N * NU;

    float acc[16];
#pragma unroll
    for (int cc = 0; cc < 16; cc++) acc[cc] = 0.f;

    for (int kt = 0; kt < 16; kt++) {
        __syncthreads();
        for (int idx = r; idx < 16 * 128; idx += 128) {
            int cc = idx >> 7, kk = idx & 127;
            us[cc][kk] = ub[(size_t)(c0 + cc) * (L * NU) + kt * 128 + kk];
        }
        __syncthreads();

#pragma unroll
        for (int jj = 0; jj < 4; jj++) {
            int j = kt * 4 + jj;
            const float4* mrow = (const float4*)(g_M[63 - j] + (size_t)r * NU);
            float m[NU];
#pragma unroll
            for (int q = 0; q < NU / 4; q++) {
                float4 w = mrow[q];
                m[4 * q + 0] = w.x; m[4 * q + 1] = w.y;
                m[4 * q + 2] = w.z; m[4 * q + 3] = w.w;
            }
#pragma unroll
            for (int v = 0; v < NU; v++) {
                float mv = m[v];
#pragma unroll
                for (int cc = 0; cc < 16; cc++)
                    acc[cc] += mv * us[cc][jj * 32 + v];
            }
        }
    }

#pragma unroll
    for (int cc = 0; cc < 16; cc++)
        WL[((size_t)b * NCHUNK + c0 + cc) * NX + r] = acc[cc];
}

// ---------------------------------------------------------------------------
// Pass 2: serial combine (unchanged).
// ---------------------------------------------------------------------------
__global__ void __launch_bounds__(NX) pass2_combine(
    const float* __restrict__ A64,
    const float* __restrict__ WL,
    float* __restrict__ XS)
{
    __shared__ float s[NX];
    const int b = blockIdx.x, i = threadIdx.x;

    float a[NX];
#pragma unroll
    for (int j = 0; j < NX; j++) a[j] = A64[i * NX + j];

    float* xsb = XS + (size_t)b * NCHUNK * NX;

    s[i] = 0.f;
    xsb[i] = 0.f;
    __syncthreads();

    for (int c = 0; c < NCHUNK - 1; c++) {
        const float4* s4 = (const float4*)s;
        float acc0 = 0.f, acc1 = 0.f, acc2 = 0.f, acc3 = 0.f;
#pragma unroll
        for (int j = 0; j < NX / 4; j++) {
            float4 v = s4[j];
            acc0 += a[4 * j + 0] * v.x;
            acc1 += a[4 * j + 1] * v.y;
            acc2 += a[4 * j + 2] * v.z;
            acc3 += a[4 * j + 3] * v.w;
        }
        float wl = WL[((size_t)b * NCHUNK + c) * NX + i];
        float ns = (acc0 + acc1) + (acc2 + acc3) + wl;
        __syncthreads();
        s[i] = ns;
        xsb[(size_t)(c + 1) * NX + i] = ns;
        __syncthreads();
    }
}

// ---------------------------------------------------------------------------
// Final sweep, dual-stream (unchanged from R12).
// ---------------------------------------------------------------------------
__global__ void __launch_bounds__(NX, 3) pass4_final(
    const float* __restrict__ V,
    const float* __restrict__ A,
    const float* __restrict__ XS,
    float* __restrict__ xout)
{
    __shared__ float xs[2][2][NX];

    const int c  = blockIdx.x;
    const int b0 = blockIdx.y;
    const int b1 = blockIdx.y + BATCH / 2;
    const int i  = threadIdx.x;

    float a[NX];
#pragma unroll
    for (int j = 0; j < NX; j++) a[j] = A[i * NX + j];

    const float* V0 = V + ((size_t)b0 * N + (size_t)c * L) * NX + i;
    const float* V1 = V + ((size_t)b1 * N + (size_t)c * L) * NX + i;
    float* x0 = xout + (size_t)b0 * (N + 1) * NX + (size_t)c * L * NX;
    float* x1 = xout + (size_t)b1 * (N + 1) * NX + (size_t)c * L * NX;

    if (c == 0) {
        xout[(size_t)b0 * (N + 1) * NX + i] = 0.0f;
        xout[(size_t)b1 * (N + 1) * NX + i] = 0.0f;
    }

    xs[0][0][i] = XS[((size_t)b0 * NCHUNK + c) * NX + i];
    xs[0][1][i] = XS[((size_t)b1 * NCHUNK + c) * NX + i];
    __syncthreads();

    float v00 = V0[0],  v01 = V0[NX];
    float v10 = V1[0],  v11 = V1[NX];

    int p = 0;
    for (int k = 0; k < L; k++) {
        const float4* xa  = (const float4*)xs[p][0];
        const float4* xbv = (const float4*)xs[p][1];
        float s00 = v00, s01 = 0.f, s02 = 0.f, s03 = 0.f;
        float s10 = v10, s11 = 0.f, s12 = 0.f, s13 = 0.f;
#pragma unroll
        for (int j = 0; j < NX / 4; j++) {
            float4 u0 = xa[j];
            float4 u1 = xbv[j];
            float aj0 = a[4 * j + 0], aj1 = a[4 * j + 1];
            float aj2 = a[4 * j + 2], aj3 = a[4 * j + 3];
            s00 += aj0 * u0.x;  s10 += aj0 * u1.x;
            s01 += aj1 * u0.y;  s11 += aj1 * u1.y;
            s02 += aj2 * u0.z;  s12 += aj2 * u1.z;
            s03 += aj3 * u0.w;  s13 += aj3 * u1.w;
        }
        float w0 = (s00 + s01) + (s02 + s03);
        float w1 = (s10 + s11) + (s12 + s13);

        v00 = v01;  v10 = v11;
        if (k + 2 < L) {
            v01 = V0[(size_t)(k + 2) * NX];
            v11 = V1[(size_t)(k + 2) * NX];
        }

        xs[p ^ 1][0][i] = w0;
        xs[p ^ 1][1][i] = w1;
        x0[(size_t)(k + 1) * NX + i] = w0;
        x1[(size_t)(k + 1) * NX + i] = w1;
        __syncthreads();
        p ^= 1;
    }
}

// ---------------------------------------------------------------------------
// Output kernel (unchanged from R11).
// ---------------------------------------------------------------------------
#define TCHUNK 32

__global__ void __launch_bounds__(256) y_kernel(
    const float* __restrict__ d,
    const float* __restrict__ C,
    const float* __restrict__ D,
    const float* __restrict__ x,
    float* __restrict__ y)
{
    __shared__ float4 Csh[NX / 4][NY];
    __shared__ float4 Dsh[NU / 4][NY];
    __shared__ float  xsh[TCHUNK][NX];
    __shared__ float  ush[TCHUNK][NU];

    const int chunk = blockIdx.x;
    const int b     = blockIdx.y;
    const int tid   = threadIdx.x;

    {
        const float4* C4 = (const float4*)C;
#pragma unroll
        for (int q = 0; q < 4; q++) {
            int f = tid + 256 * q;
            Csh[f & 31][f >> 5] = C4[f];
        }
        const float4* D4 = (const float4*)D;
        Dsh[tid & 7][tid >> 3] = D4[tid];
    }
    {
        const float4* xg4 = (const float4*)(x + (size_t)b * (N + 1) * NX
                                              + (size_t)chunk * TCHUNK * NX);
        float4* xs4 = (float4*)&xsh[0][0];
#pragma unroll
        for (int q = 0; q < 4; q++)
            xs4[tid + 256 * q] = xg4[tid + 256 * q];

        const float4* ug4 = (const float4*)(d + (size_t)b * N * NU
                                              + (size_t)chunk * TCHUNK * NU);
        ((float4*)&ush[0][0])[tid] = ug4[tid];
    }
    __syncthreads();

    const int o = tid & 31;
    const int w = tid >> 5;

    float* yb = y + (size_t)b * N * NY + (size_t)chunk * TCHUNK * NY;

#pragma unroll
    for (int tt = 0; tt < 4; tt++) {
        const int t = w * 4 + tt;
        const float4* xr = (const float4*)xsh[t];
        const float4* ur = (const float4*)ush[t];
        float a0 = 0.f, a1 = 0.f, a2 = 0.f, a3 = 0.f;
#pragma unroll
        for (int j4 = 0; j4 < NX / 4; j4++) {
            float4 v = xr[j4];
            float4 cj = Csh[j4][o];
            a0 += cj.x * v.x;
            a1 += cj.y * v.y;
            a2 += cj.z * v.z;
            a3 += cj.w * v.w;
        }
#pragma unroll
        for (int q = 0; q < NU / 4; q++) {
            float4 v = ur[q];
            float4 dq = Dsh[q][o];
            a0 += dq.x * v.x;
            a1 += dq.y * v.y;
            a2 += dq.z * v.z;
            a3 += dq.w * v.w;
        }
        yb[(size_t)t * NY + o] = (a0 + a1) + (a2 + a3);
    }
}

// ---------------------------------------------------------------------------
extern "C" void kernel_launch(void* const* d_in, const int* in_sizes, int n_in,
                              void* d_out, int out_size)
{
    const float* d = (const float*)d_in[0];
    const float* A = (const float*)d_in[1];
    const float* B = (const float*)d_in[2];
    const float* C = (const float*)d_in[3];
    const float* D = (const float*)d_in[4];

    float* y = (float*)d_out;
    float* x = (float*)d_out + Y_ELEMS;

    float* PA;  cudaGetSymbolAddress((void**)&PA, g_PA);
    float* WL;  cudaGetSymbolAddress((void**)&WL, g_WL);
    float* XS;  cudaGetSymbolAddress((void**)&XS, g_XS);
    float* V;   cudaGetSymbolAddress((void**)&V,  g_V);

    // #1-#3: A^2, A^4, A^8
    matsq<<<NX, NX>>>(A,           PA + 0 * MS);
    matsq<<<NX, NX>>>(PA + 0 * MS, PA + 1 * MS);
    matsq<<<NX, NX>>>(PA + 1 * MS, PA + 2 * MS);

    // #4: PROBE — small-grid clone of the sweep so ncu (captures launch #4)
    // finally profiles it. Reads stale-but-deterministic XS/V; every x value
    // it writes is overwritten by the real pass4 below.
    {
        dim3 g(4, BATCH / 2);
        pass4_final<<<g, NX>>>(V, A, XS, x);
    }

    // #5-#7: A^16, A^32, A^64
    matsq<<<NX, NX>>>(PA + 2 * MS, PA + 3 * MS);
    matsq<<<NX, NX>>>(PA + 3 * MS, PA + 4 * MS);
    matsq<<<NX, NX>>>(PA + 4 * MS, PA + 5 * MS);

    // #8: V = B u (v2: 2 rows/thread)
    {
        dim3 g(N / 32, BATCH);
        v_kernel<<<g, NX>>>(d, B, V);
    }

    // #9: all M[m] = A^m B in one launch
    build_M<<<64, NX>>>(A, B);

    // #10: chunk-end contributions via GEMM
    {
        dim3 g(NCHUNK / 16, BATCH);
        gemm_wl<<<g, NX>>>(d, WL);
    }

    // #11: serial chunk combine -> start states
    pass2_combine<<<BATCH, NX>>>(PA + 5 * MS, WL, XS);

    // #12: dual-stream seeded sweep produces exact x
    {
        dim3 g(NCHUNK, BATCH / 2);
        pass4_final<<<g, NX>>>(V, A, XS, x);
    }

    // #13: output projection
    {
        dim3 g(N / TCHUNK, BATCH);
        y_kernel<<<g, 256>>>(d, C, D, x, y);
    }
}

// round 15
// speedup vs baseline: 1.1087x; 1.1087x over previous
#include <cuda_runtime.h>

#define BATCH 64
#define N     4096
#define NX    128
#define NU    32
#define NY    32
#define L     64
#define NCHUNK (N / L)     // 64
#define MS    (NX * NX)    // 16384

#define Y_ELEMS ((size_t)BATCH * N * NY)

// Scratch (no cudaMalloc allowed)
__device__ float g_PA[6][MS];               // A^2, A^4, A^8, A^16, A^32, A^64
__device__ float g_M[64][NX * NU];          // M[m] = A^m * B   (128x32 each)
__device__ float g_WL[BATCH * NCHUNK * NX]; // chunk-local end contributions
__device__ float g_XS[BATCH * NCHUNK * NX]; // chunk start states x_{cL}
__device__ float g_V[(size_t)BATCH * N * NX]; // V[b][t] = B u_t

// ---------------------------------------------------------------------------
// 128x128 matrix square: out = in * in. grid=128 (row), block=128 (col).
// ---------------------------------------------------------------------------
__global__ void __launch_bounds__(NX) matsq(const float* __restrict__ in,
                                            float* __restrict__ out)
{
    __shared__ float row[NX];
    const int r = blockIdx.x, c = threadIdx.x;
    row[c] = in[r * NX + c];
    __syncthreads();
    float acc = 0.f;
#pragma unroll 16
    for (int j = 0; j < NX; j++) acc += row[j] * in[j * NX + c];
    out[r * NX + c] = acc;
}

// ---------------------------------------------------------------------------
// build_M: ONE launch for all M[m] = A^m B, m = 0..63. grid=64, block=128.
// ---------------------------------------------------------------------------
__global__ void __launch_bounds__(NX) build_M(
    const float* __restrict__ A,
    const float* __restrict__ B)
{
    __shared__ float cur[NX * NU];   // 16 KB
    const int m = blockIdx.x, r = threadIdx.x;

    for (int idx = r; idx < NX * NU; idx += NX) cur[idx] = B[idx];
    __syncthreads();

    for (int s = 0; s < 6; s++) {
        if ((m >> s) & 1) {
            const float* P = (s == 0) ? A : g_PA[s - 1];
            float a[NX];
            {
                const float4* p4 = (const float4*)(P + (size_t)r * NX);
#pragma unroll
                for (int j = 0; j < NX / 4; j++) {
                    float4 v = p4[j];
                    a[4 * j + 0] = v.x; a[4 * j + 1] = v.y;
                    a[4 * j + 2] = v.z; a[4 * j + 3] = v.w;
                }
            }
            float acc[NU];
#pragma unroll
            for (int v = 0; v < NU; v++) acc[v] = 0.f;
#pragma unroll 4
            for (int j = 0; j < NX; j++) {
                float pj = a[j];
#pragma unroll
                for (int v = 0; v < NU; v++) acc[v] += pj * cur[j * NU + v];
            }
            __syncthreads();
#pragma unroll
            for (int v = 0; v < NU; v++) cur[r * NU + v] = acc[v];
            __syncthreads();
        }
    }

    float* Mo = g_M[m];
    for (int idx = r; idx < NX * NU; idx += NX) Mo[idx] = cur[idx];
}

// ---------------------------------------------------------------------------
// V kernel v2 (unchanged from R13): 2 B-rows per thread.
// ---------------------------------------------------------------------------
__global__ void __launch_bounds__(NX) v_kernel(
    const float* __restrict__ d,
    const float* __restrict__ B,
    float* __restrict__ V)
{
    __shared__ float us[32][NU];
    const int t0  = blockIdx.x * 32;
    const int b   = blockIdx.y;
    const int tid = threadIdx.x;
    const int h   = tid >> 6;
    const int r2  = tid & 63;

    {
        const float4* ug4 = (const float4*)(d + ((size_t)b * N + t0) * NU);
        float4* us4 = (float4*)&us[0][0];
#pragma unroll
        for (int q = 0; q < (32 * NU / 4) / NX; q++)
            us4[tid + NX * q] = ug4[tid + NX * q];
    }
    __syncthreads();

    float ba[NU], bc[NU];
    {
        const float4* b4a = (const float4*)(B + (size_t)(2 * r2) * NU);
        const float4* b4b = (const float4*)(B + (size_t)(2 * r2 + 1) * NU);
#pragma unroll
        for (int q = 0; q < NU / 4; q++) {
            float4 v = b4a[q];
            ba[4 * q + 0] = v.x; ba[4 * q + 1] = v.y;
            ba[4 * q + 2] = v.z; ba[4 * q + 3] = v.w;
            float4 w = b4b[q];
            bc[4 * q + 0] = w.x; bc[4 * q + 1] = w.y;
            bc[4 * q + 2] = w.z; bc[4 * q + 3] = w.w;
        }
    }

    float2* Vb = (float2*)(V + ((size_t)b * N + t0) * NX);
#pragma unroll 4
    for (int t = 0; t < 16; t++) {
        const int tt = h * 16 + t;
        const float4* u4 = (const float4*)us[tt];
        float a0 = 0.f, a1 = 0.f, a2 = 0.f, a3 = 0.f;
        float c0 = 0.f, c1 = 0.f, c2 = 0.f, c3 = 0.f;
#pragma unroll
        for (int q = 0; q < NU / 4; q++) {
            float4 v = u4[q];
            a0 += ba[4 * q + 0] * v.x;  c0 += bc[4 * q + 0] * v.x;
            a1 += ba[4 * q + 1] * v.y;  c1 += bc[4 * q + 1] * v.y;
            a2 += ba[4 * q + 2] * v.z;  c2 += bc[4 * q + 2] * v.z;
            a3 += ba[4 * q + 3] * v.w;  c3 += bc[4 * q + 3] * v.w;
        }
        float2 out;
        out.x = (a0 + a1) + (a2 + a3);
        out.y = (c0 + c1) + (c2 + c3);
        Vb[(size_t)tt * (NX / 2) + r2] = out;
    }
}

// ---------------------------------------------------------------------------
// GEMM for chunk-end contributions (unchanged).
// ---------------------------------------------------------------------------
__global__ void __launch_bounds__(NX) gemm_wl(
    const float* __restrict__ d,
    float* __restrict__ WL)
{
    __shared__ float us[16][128];

    const int c0 = blockIdx.x * 16;
    const int b  = blockIdx.y;
    const int r  = threadIdx.x;

    const float* ub = d + (size_t)b * N * NU;

    float acc[16];
#pragma unroll
    for (int cc = 0; cc < 16; cc++) acc[cc] = 0.f;

    for (int kt = 0; kt < 16; kt++) {
        __syncthreads();
        for (int idx = r; idx < 16 * 128; idx += 128) {
            int cc = idx >> 7, kk = idx & 127;
            us[cc][kk] = ub[(size_t)(c0 + cc) * (L * NU) + kt * 128 + kk];
        }
        __syncthreads();

#pragma unroll
        for (int jj = 0; jj < 4; jj++) {
            int j = kt * 4 + jj;
            const float4* mrow = (const float4*)(g_M[63 - j] + (size_t)r * NU);
            float m[NU];
#pragma unroll
            for (int q = 0; q < NU / 4; q++) {
                float4 w = mrow[q];
                m[4 * q + 0] = w.x; m[4 * q + 1] = w.y;
                m[4 * q + 2] = w.z; m[4 * q + 3] = w.w;
            }
#pragma unroll
            for (int v = 0; v < NU; v++) {
                float mv = m[v];
#pragma unroll
                for (int cc = 0; cc < 16; cc++)
                    acc[cc] += mv * us[cc][jj * 32 + v];
            }
        }
    }

#pragma unroll
    for (int cc = 0; cc < 16; cc++)
        WL[((size_t)b * NCHUNK + c0 + cc) * NX + r] = acc[cc];
}

// ---------------------------------------------------------------------------
// Pass 2: serial combine (unchanged).
// ---------------------------------------------------------------------------
__global__ void __launch_bounds__(NX) pass2_combine(
    const float* __restrict__ A64,
    const float* __restrict__ WL,
    float* __restrict__ XS)
{
    __shared__ float s[NX];
    const int b = blockIdx.x, i = threadIdx.x;

    float a[NX];
#pragma unroll
    for (int j = 0; j < NX; j++) a[j] = A64[i * NX + j];

    float* xsb = XS + (size_t)b * NCHUNK * NX;

    s[i] = 0.f;
    xsb[i] = 0.f;
    __syncthreads();

    for (int c = 0; c < NCHUNK - 1; c++) {
        const float4* s4 = (const float4*)s;
        float acc0 = 0.f, acc1 = 0.f, acc2 = 0.f, acc3 = 0.f;
#pragma unroll
        for (int j = 0; j < NX / 4; j++) {
            float4 v = s4[j];
            acc0 += a[4 * j + 0] * v.x;
            acc1 += a[4 * j + 1] * v.y;
            acc2 += a[4 * j + 2] * v.z;
            acc3 += a[4 * j + 3] * v.w;
        }
        float wl = WL[((size_t)b * NCHUNK + c) * NX + i];
        float ns = (acc0 + acc1) + (acc2 + acc3) + wl;
        __syncthreads();
        s[i] = ns;
        xsb[(size_t)(c + 1) * NX + i] = ns;
        __syncthreads();
    }
}

// ---------------------------------------------------------------------------
// FUSED final sweep + y projection.
// Scan part: identical dual-stream recurrence (R12). Then the SAME CTA
// computes y for its own 64 timesteps x 2 streams, reading x rows it just
// wrote (CTA-local, visible after __syncthreads; x[cL] from saved smem seed
// to avoid the cross-CTA race on chunk boundaries).
// ---------------------------------------------------------------------------
__global__ void __launch_bounds__(NX, 3) pass4_fused(
    const float* __restrict__ V,
    const float* __restrict__ A,
    const float* __restrict__ XS,
    const float* __restrict__ d,
    const float* __restrict__ C,
    const float* __restrict__ Dm,
    float* __restrict__ xout,
    float* __restrict__ yout)
{
    __shared__ float  xs[2][2][NX];     // 1 KB  scan double buffer
    __shared__ float  xseed[2][NX];     // 1 KB  chunk start states
    __shared__ float4 Csh[NX / 4][NY];  // 16 KB C transposed
    __shared__ float4 Dsh[NU / 4][NY];  // 4 KB  D transposed
    __shared__ float  xt[16][NX];       // 8 KB  y-phase x tile
    __shared__ float  ut[16][NU];       // 2 KB  y-phase u tile

    const int c  = blockIdx.x;
    const int b0 = blockIdx.y;
    const int b1 = blockIdx.y + BATCH / 2;
    const int i  = threadIdx.x;

    // Stage C / D once (smem otherwise idle during scan)
    {
        const float4* C4 = (const float4*)C;
#pragma unroll
        for (int q = 0; q < 8; q++) {
            int f = i + NX * q;              // 0..1023
            Csh[f & 31][f >> 5] = C4[f];
        }
        const float4* D4 = (const float4*)Dm;
#pragma unroll
        for (int q = 0; q < 2; q++) {
            int f = i + NX * q;              // 0..255
            Dsh[f & 7][f >> 3] = D4[f];
        }
    }

    float a[NX];
#pragma unroll
    for (int j = 0; j < NX; j++) a[j] = A[i * NX + j];

    const float* V0 = V + ((size_t)b0 * N + (size_t)c * L) * NX + i;
    const float* V1 = V + ((size_t)b1 * N + (size_t)c * L) * NX + i;
    float* x0 = xout + (size_t)b0 * (N + 1) * NX + (size_t)c * L * NX;
    float* x1 = xout + (size_t)b1 * (N + 1) * NX + (size_t)c * L * NX;

    if (c == 0) {
        xout[(size_t)b0 * (N + 1) * NX + i] = 0.0f;
        xout[(size_t)b1 * (N + 1) * NX + i] = 0.0f;
    }

    {
        float s0 = XS[((size_t)b0 * NCHUNK + c) * NX + i];
        float s1 = XS[((size_t)b1 * NCHUNK + c) * NX + i];
        xs[0][0][i] = s0;  xseed[0][i] = s0;
        xs[0][1][i] = s1;  xseed[1][i] = s1;
    }
    __syncthreads();

    float v00 = V0[0],  v01 = V0[NX];
    float v10 = V1[0],  v11 = V1[NX];

    int p = 0;
    for (int k = 0; k < L; k++) {
        const float4* xa  = (const float4*)xs[p][0];
        const float4* xbv = (const float4*)xs[p][1];
        float s00 = v00, s01 = 0.f, s02 = 0.f, s03 = 0.f;
        float s10 = v10, s11 = 0.f, s12 = 0.f, s13 = 0.f;
#pragma unroll
        for (int j = 0; j < NX / 4; j++) {
            float4 u0 = xa[j];
            float4 u1 = xbv[j];
            float aj0 = a[4 * j + 0], aj1 = a[4 * j + 1];
            float aj2 = a[4 * j + 2], aj3 = a[4 * j + 3];
            s00 += aj0 * u0.x;  s10 += aj0 * u1.x;
            s01 += aj1 * u0.y;  s11 += aj1 * u1.y;
            s02 += aj2 * u0.z;  s12 += aj2 * u1.z;
            s03 += aj3 * u0.w;  s13 += aj3 * u1.w;
        }
        float w0 = (s00 + s01) + (s02 + s03);
        float w1 = (s10 + s11) + (s12 + s13);

        v00 = v01;  v10 = v11;
        if (k + 2 < L) {
            v01 = V0[(size_t)(k + 2) * NX];
            v11 = V1[(size_t)(k + 2) * NX];
        }

        xs[p ^ 1][0][i] = w0;
        xs[p ^ 1][1][i] = w1;
        x0[(size_t)(k + 1) * NX + i] = w0;
        x1[(size_t)(k + 1) * NX + i] = w1;
        __syncthreads();
        p ^= 1;
    }

    // ---- y-phase: y[b][cL+t] = C x_{cL+t} + D u_{cL+t}, t = 0..63 ----
    const int o = i & 31;   // output channel
    const int w = i >> 5;   // warp -> 4 timesteps per tile

#pragma unroll 1
    for (int s = 0; s < 2; s++) {
        const int b = s ? b1 : b0;
        const float* xg = xout + (size_t)b * (N + 1) * NX + (size_t)c * L * NX;
        const float* ug = d + ((size_t)b * N + (size_t)c * L) * NU;
        float* yb = yout + ((size_t)b * N + (size_t)c * L) * NY;

#pragma unroll 1
        for (int tile = 0; tile < 4; tile++) {
            __syncthreads();   // protect xt/ut reuse
            {
                const float4* xg4 = (const float4*)(xg + (size_t)tile * 16 * NX);
                float4* xt4 = (float4*)&xt[0][0];
#pragma unroll
                for (int q = 0; q < 4; q++)
                    xt4[i + NX * q] = xg4[i + NX * q];

                const float4* ug4 = (const float4*)(ug + (size_t)tile * 16 * NU);
                ((float4*)&ut[0][0])[i] = ug4[i];
            }
            __syncthreads();
            if (tile == 0) {
                // row 0 of tile 0 is x[cL]: cross-CTA racy in global; use seed
                xt[0][i] = xseed[s][i];
                __syncthreads();
            }

#pragma unroll
            for (int tt = 0; tt < 4; tt++) {
                const int trow = w * 4 + tt;   // 0..15 within tile
                const float4* xr = (const float4*)xt[trow];
                const float4* ur = (const float4*)ut[trow];
                float a0 = 0.f, a1 = 0.f, a2 = 0.f, a3 = 0.f;
#pragma unroll
                for (int j4 = 0; j4 < NX / 4; j4++) {
                    float4 v  = xr[j4];
                    float4 cj = Csh[j4][o];
                    a0 += cj.x * v.x;
                    a1 += cj.y * v.y;
                    a2 += cj.z * v.z;
                    a3 += cj.w * v.w;
                }
#pragma unroll
                for (int q = 0; q < NU / 4; q++) {
                    float4 v  = ur[q];
                    float4 dq = Dsh[q][o];
                    a0 += dq.x * v.x;
                    a1 += dq.y * v.y;
                    a2 += dq.z * v.z;
                    a3 += dq.w * v.w;
                }
                yb[(size_t)(tile * 16 + trow) * NY + o] = (a0 + a1) + (a2 + a3);
            }
        }
    }
}

// ---------------------------------------------------------------------------
extern "C" void kernel_launch(void* const* d_in, const int* in_sizes, int n_in,
                              void* d_out, int out_size)
{
    const float* d = (const float*)d_in[0];
    const float* A = (const float*)d_in[1];
    const float* B = (const float*)d_in[2];
    const float* C = (const float*)d_in[3];
    const float* D = (const float*)d_in[4];

    float* y = (float*)d_out;
    float* x = (float*)d_out + Y_ELEMS;

    float* PA;  cudaGetSymbolAddress((void**)&PA, g_PA);
    float* WL;  cudaGetSymbolAddress((void**)&WL, g_WL);
    float* XS;  cudaGetSymbolAddress((void**)&XS, g_XS);
    float* V;   cudaGetSymbolAddress((void**)&V,  g_V);

    // #1-#3: A^2, A^4, A^8
    matsq<<<NX, NX>>>(A,           PA + 0 * MS);
    matsq<<<NX, NX>>>(PA + 0 * MS, PA + 1 * MS);
    matsq<<<NX, NX>>>(PA + 1 * MS, PA + 2 * MS);

    // #4 (ncu captures launch #4): V = B u  (v2)
    {
        dim3 g(N / 32, BATCH);
        v_kernel<<<g, NX>>>(d, B, V);
    }

    // #5-#7: A^16, A^32, A^64
    matsq<<<NX, NX>>>(PA + 2 * MS, PA + 3 * MS);
    matsq<<<NX, NX>>>(PA + 3 * MS, PA + 4 * MS);
    matsq<<<NX, NX>>>(PA + 4 * MS, PA + 5 * MS);

    // #8: all M[m] = A^m B in one launch
    build_M<<<64, NX>>>(A, B);

    // #9: chunk-end contributions via GEMM
    {
        dim3 g(NCHUNK / 16, BATCH);
        gemm_wl<<<g, NX>>>(d, WL);
    }

    // #10: serial chunk combine -> start states
    pass2_combine<<<BATCH, NX>>>(PA + 5 * MS, WL, XS);

    // #11: fused sweep + y projection
    {
        dim3 g(NCHUNK, BATCH / 2);
        pass4_fused<<<g, NX>>>(V, A, XS, d, C, D, x, y);
    }
}

// round 16
// speedup vs baseline: 1.1147x; 1.0054x over previous
#include <cuda_runtime.h>

#define BATCH 64
#define N     4096
#define NX    128
#define NU    32
#define NY    32
#define L     64
#define NCHUNK (N / L)     // 64
#define MS    (NX * NX)    // 16384

#define Y_ELEMS ((size_t)BATCH * N * NY)

// Scratch (no cudaMalloc allowed)
__device__ float g_PA[6][MS];               // A^2, A^4, A^8, A^16, A^32, A^64
__device__ float g_M[64][NX * NU];          // M[m] = A^m * B   (128x32 each)
__device__ float g_WL[BATCH * NCHUNK * NX]; // chunk-local end contributions
__device__ float g_XS[BATCH * NCHUNK * NX]; // chunk start states x_{cL}
__device__ float g_V[(size_t)BATCH * N * NX]; // V[b][t] = B u_t

// ---------------------------------------------------------------------------
// 128x128 matrix square: out = in * in. grid=128 (row), block=128 (col).
// ---------------------------------------------------------------------------
__global__ void __launch_bounds__(NX) matsq(const float* __restrict__ in,
                                            float* __restrict__ out)
{
    __shared__ float row[NX];
    const int r = blockIdx.x, c = threadIdx.x;
    row[c] = in[r * NX + c];
    __syncthreads();
    float acc = 0.f;
#pragma unroll 16
    for (int j = 0; j < NX; j++) acc += row[j] * in[j * NX + c];
    out[r * NX + c] = acc;
}

// ---------------------------------------------------------------------------
// build_M: ONE launch for all M[m] = A^m B, m = 0..63. grid=64, block=128.
// ---------------------------------------------------------------------------
__global__ void __launch_bounds__(NX) build_M(
    const float* __restrict__ A,
    const float* __restrict__ B)
{
    __shared__ float cur[NX * NU];   // 16 KB
    const int m = blockIdx.x, r = threadIdx.x;

    for (int idx = r; idx < NX * NU; idx += NX) cur[idx] = B[idx];
    __syncthreads();

    for (int s = 0; s < 6; s++) {
        if ((m >> s) & 1) {
            const float* P = (s == 0) ? A : g_PA[s - 1];
            float a[NX];
            {
                const float4* p4 = (const float4*)(P + (size_t)r * NX);
#pragma unroll
                for (int j = 0; j < NX / 4; j++) {
                    float4 v = p4[j];
                    a[4 * j + 0] = v.x; a[4 * j + 1] = v.y;
                    a[4 * j + 2] = v.z; a[4 * j + 3] = v.w;
                }
            }
            float acc[NU];
#pragma unroll
            for (int v = 0; v < NU; v++) acc[v] = 0.f;
#pragma unroll 4
            for (int j = 0; j < NX; j++) {
                float pj = a[j];
#pragma unroll
                for (int v = 0; v < NU; v++) acc[v] += pj * cur[j * NU + v];
            }
            __syncthreads();
#pragma unroll
            for (int v = 0; v < NU; v++) cur[r * NU + v] = acc[v];
            __syncthreads();
        }
    }

    float* Mo = g_M[m];
    for (int idx = r; idx < NX * NU; idx += NX) Mo[idx] = cur[idx];
}

// ---------------------------------------------------------------------------
// V kernel v1 (REVERTED — measured 93us vs v2's 108us):
// V[b][t][r] = B[r][:] . u[b][t][:]. grid=(N/32, BATCH), block=128.
// ---------------------------------------------------------------------------
__global__ void __launch_bounds__(NX) v_kernel(
    const float* __restrict__ d,
    const float* __restrict__ B,
    float* __restrict__ V)
{
    __shared__ float us[32][NU];
    const int t0 = blockIdx.x * 32;
    const int b  = blockIdx.y;
    const int r  = threadIdx.x;

    {
        const float4* ug4 = (const float4*)(d + ((size_t)b * N + t0) * NU);
        float4* us4 = (float4*)&us[0][0];
#pragma unroll
        for (int q = 0; q < (32 * NU / 4) / NX; q++)
            us4[r + NX * q] = ug4[r + NX * q];
    }
    __syncthreads();

    float bb[NU];
    {
        const float4* b4 = (const float4*)(B + (size_t)r * NU);
#pragma unroll
        for (int q = 0; q < NU / 4; q++) {
            float4 v = b4[q];
            bb[4 * q + 0] = v.x; bb[4 * q + 1] = v.y;
            bb[4 * q + 2] = v.z; bb[4 * q + 3] = v.w;
        }
    }

    float* Vb = V + ((size_t)b * N + t0) * NX;
#pragma unroll 4
    for (int t = 0; t < 32; t++) {
        const float4* u4 = (const float4*)us[t];
        float a0 = 0.f, a1 = 0.f, a2 = 0.f, a3 = 0.f;
#pragma unroll
        for (int q = 0; q < NU / 4; q++) {
            float4 v = u4[q];
            a0 += bb[4 * q + 0] * v.x;
            a1 += bb[4 * q + 1] * v.y;
            a2 += bb[4 * q + 2] * v.z;
            a3 += bb[4 * q + 3] * v.w;
        }
        Vb[(size_t)t * NX + r] = (a0 + a1) + (a2 + a3);
    }
}

// ---------------------------------------------------------------------------
// GEMM for chunk-end contributions (unchanged).
// ---------------------------------------------------------------------------
__global__ void __launch_bounds__(NX) gemm_wl(
    const float* __restrict__ d,
    float* __restrict__ WL)
{
    __shared__ float us[16][128];

    const int c0 = blockIdx.x * 16;
    const int b  = blockIdx.y;
    const int r  = threadIdx.x;

    const float* ub = d + (size_t)b * N * NU;

    float acc[16];
#pragma unroll
    for (int cc = 0; cc < 16; cc++) acc[cc] = 0.f;

    for (int kt = 0; kt < 16; kt++) {
        __syncthreads();
        for (int idx = r; idx < 16 * 128; idx += 128) {
            int cc = idx >> 7, kk = idx & 127;
            us[cc][kk] = ub[(size_t)(c0 + cc) * (L * NU) + kt * 128 + kk];
        }
        __syncthreads();

#pragma unroll
        for (int jj = 0; jj < 4; jj++) {
            int j = kt * 4 + jj;
            const float4* mrow = (const float4*)(g_M[63 - j] + (size_t)r * NU);
            float m[NU];
#pragma unroll
            for (int q = 0; q < NU / 4; q++) {
                float4 w = mrow[q];
                m[4 * q + 0] = w.x; m[4 * q + 1] = w.y;
                m[4 * q + 2] = w.z; m[4 * q + 3] = w.w;
            }
#pragma unroll
            for (int v = 0; v < NU; v++) {
                float mv = m[v];
#pragma unroll
                for (int cc = 0; cc < 16; cc++)
                    acc[cc] += mv * us[cc][jj * 32 + v];
            }
        }
    }

#pragma unroll
    for (int cc = 0; cc < 16; cc++)
        WL[((size_t)b * NCHUNK + c0 + cc) * NX + r] = acc[cc];
}

// ---------------------------------------------------------------------------
// Pass 2: serial combine (unchanged).
// ---------------------------------------------------------------------------
__global__ void __launch_bounds__(NX) pass2_combine(
    const float* __restrict__ A64,
    const float* __restrict__ WL,
    float* __restrict__ XS)
{
    __shared__ float s[NX];
    const int b = blockIdx.x, i = threadIdx.x;

    float a[NX];
#pragma unroll
    for (int j = 0; j < NX; j++) a[j] = A64[i * NX + j];

    float* xsb = XS + (size_t)b * NCHUNK * NX;

    s[i] = 0.f;
    xsb[i] = 0.f;
    __syncthreads();

    for (int c = 0; c < NCHUNK - 1; c++) {
        const float4* s4 = (const float4*)s;
        float acc0 = 0.f, acc1 = 0.f, acc2 = 0.f, acc3 = 0.f;
#pragma unroll
        for (int j = 0; j < NX / 4; j++) {
            float4 v = s4[j];
            acc0 += a[4 * j + 0] * v.x;
            acc1 += a[4 * j + 1] * v.y;
            acc2 += a[4 * j + 2] * v.z;
            acc3 += a[4 * j + 3] * v.w;
        }
        float wl = WL[((size_t)b * NCHUNK + c) * NX + i];
        float ns = (acc0 + acc1) + (acc2 + acc3) + wl;
        __syncthreads();
        s[i] = ns;
        xsb[(size_t)(c + 1) * NX + i] = ns;
        __syncthreads();
    }
}

// ---------------------------------------------------------------------------
// FUSED final sweep + y projection, V prefetch depth 4 (was 2).
// ---------------------------------------------------------------------------
__global__ void __launch_bounds__(NX, 3) pass4_fused(
    const float* __restrict__ V,
    const float* __restrict__ A,
    const float* __restrict__ XS,
    const float* __restrict__ d,
    const float* __restrict__ C,
    const float* __restrict__ Dm,
    float* __restrict__ xout,
    float* __restrict__ yout)
{
    __shared__ float  xs[2][2][NX];     // scan double buffer
    __shared__ float  xseed[2][NX];     // chunk start states
    __shared__ float4 Csh[NX / 4][NY];  // C transposed
    __shared__ float4 Dsh[NU / 4][NY];  // D transposed
    __shared__ float  xt[16][NX];       // y-phase x tile
    __shared__ float  ut[16][NU];       // y-phase u tile

    const int c  = blockIdx.x;
    const int b0 = blockIdx.y;
    const int b1 = blockIdx.y + BATCH / 2;
    const int i  = threadIdx.x;

    // Stage C / D once
    {
        const float4* C4 = (const float4*)C;
#pragma unroll
        for (int q = 0; q < 8; q++) {
            int f = i + NX * q;
            Csh[f & 31][f >> 5] = C4[f];
        }
        const float4* D4 = (const float4*)Dm;
#pragma unroll
        for (int q = 0; q < 2; q++) {
            int f = i + NX * q;
            Dsh[f & 7][f >> 3] = D4[f];
        }
    }

    float a[NX];
#pragma unroll
    for (int j = 0; j < NX; j++) a[j] = A[i * NX + j];

    const float* V0 = V + ((size_t)b0 * N + (size_t)c * L) * NX + i;
    const float* V1 = V + ((size_t)b1 * N + (size_t)c * L) * NX + i;
    float* x0 = xout + (size_t)b0 * (N + 1) * NX + (size_t)c * L * NX;
    float* x1 = xout + (size_t)b1 * (N + 1) * NX + (size_t)c * L * NX;

    if (c == 0) {
        xout[(size_t)b0 * (N + 1) * NX + i] = 0.0f;
        xout[(size_t)b1 * (N + 1) * NX + i] = 0.0f;
    }

    {
        float s0 = XS[((size_t)b0 * NCHUNK + c) * NX + i];
        float s1 = XS[((size_t)b1 * NCHUNK + c) * NX + i];
        xs[0][0][i] = s0;  xseed[0][i] = s0;
        xs[0][1][i] = s1;  xseed[1][i] = s1;
    }
    __syncthreads();

    // V prefetch ring, depth 4 (L = 64 >= 4 always)
    float va0 = V0[0 * NX], va1 = V0[1 * NX], va2 = V0[2 * NX], va3 = V0[3 * NX];
    float vb0 = V1[0 * NX], vb1 = V1[1 * NX], vb2 = V1[2 * NX], vb3 = V1[3 * NX];

    int p = 0;
    for (int k = 0; k < L; k++) {
        const float4* xa  = (const float4*)xs[p][0];
        const float4* xbv = (const float4*)xs[p][1];
        float s00 = va0, s01 = 0.f, s02 = 0.f, s03 = 0.f;
        float s10 = vb0, s11 = 0.f, s12 = 0.f, s13 = 0.f;
#pragma unroll
        for (int j = 0; j < NX / 4; j++) {
            float4 u0 = xa[j];
            float4 u1 = xbv[j];
            float aj0 = a[4 * j + 0], aj1 = a[4 * j + 1];
            float aj2 = a[4 * j + 2], aj3 = a[4 * j + 3];
            s00 += aj0 * u0.x;  s10 += aj0 * u1.x;
            s01 += aj1 * u0.y;  s11 += aj1 * u1.y;
            s02 += aj2 * u0.z;  s12 += aj2 * u1.z;
            s03 += aj3 * u0.w;  s13 += aj3 * u1.w;
        }
        float w0 = (s00 + s01) + (s02 + s03);
        float w1 = (s10 + s11) + (s12 + s13);

        // rotate prefetch ring; fetch V_{k+4}
        va0 = va1;  va1 = va2;  va2 = va3;
        vb0 = vb1;  vb1 = vb2;  vb2 = vb3;
        if (k + 4 < L) {
            va3 = V0[(size_t)(k + 4) * NX];
            vb3 = V1[(size_t)(k + 4) * NX];
        }

        xs[p ^ 1][0][i] = w0;
        xs[p ^ 1][1][i] = w1;
        x0[(size_t)(k + 1) * NX + i] = w0;
        x1[(size_t)(k + 1) * NX + i] = w1;
        __syncthreads();
        p ^= 1;
    }

    // ---- y-phase (unchanged from R15) ----
    const int o = i & 31;
    const int w = i >> 5;

#pragma unroll 1
    for (int s = 0; s < 2; s++) {
        const int b = s ? b1 : b0;
        const float* xg = xout + (size_t)b * (N + 1) * NX + (size_t)c * L * NX;
        const float* ug = d + ((size_t)b * N + (size_t)c * L) * NU;
        float* yb = yout + ((size_t)b * N + (size_t)c * L) * NY;

#pragma unroll 1
        for (int tile = 0; tile < 4; tile++) {
            __syncthreads();
            {
                const float4* xg4 = (const float4*)(xg + (size_t)tile * 16 * NX);
                float4* xt4 = (float4*)&xt[0][0];
#pragma unroll
                for (int q = 0; q < 4; q++)
                    xt4[i + NX * q] = xg4[i + NX * q];

                const float4* ug4 = (const float4*)(ug + (size_t)tile * 16 * NU);
                ((float4*)&ut[0][0])[i] = ug4[i];
            }
            __syncthreads();
            if (tile == 0) {
                xt[0][i] = xseed[s][i];
                __syncthreads();
            }

#pragma unroll
            for (int tt = 0; tt < 4; tt++) {
                const int trow = w * 4 + tt;
                const float4* xr = (const float4*)xt[trow];
                const float4* ur = (const float4*)ut[trow];
                float a0 = 0.f, a1 = 0.f, a2 = 0.f, a3 = 0.f;
#pragma unroll
                for (int j4 = 0; j4 < NX / 4; j4++) {
                    float4 v  = xr[j4];
                    float4 cj = Csh[j4][o];
                    a0 += cj.x * v.x;
                    a1 += cj.y * v.y;
                    a2 += cj.z * v.z;
                    a3 += cj.w * v.w;
                }
#pragma unroll
                for (int q = 0; q < NU / 4; q++) {
                    float4 v  = ur[q];
                    float4 dq = Dsh[q][o];
                    a0 += dq.x * v.x;
                    a1 += dq.y * v.y;
                    a2 += dq.z * v.z;
                    a3 += dq.w * v.w;
                }
                yb[(size_t)(tile * 16 + trow) * NY + o] = (a0 + a1) + (a2 + a3);
            }
        }
    }
}

// ---------------------------------------------------------------------------
extern "C" void kernel_launch(void* const* d_in, const int* in_sizes, int n_in,
                              void* d_out, int out_size)
{
    const float* d = (const float*)d_in[0];
    const float* A = (const float*)d_in[1];
    const float* B = (const float*)d_in[2];
    const float* C = (const float*)d_in[3];
    const float* D = (const float*)d_in[4];

    float* y = (float*)d_out;
    float* x = (float*)d_out + Y_ELEMS;

    float* PA;  cudaGetSymbolAddress((void**)&PA, g_PA);
    float* WL;  cudaGetSymbolAddress((void**)&WL, g_WL);
    float* XS;  cudaGetSymbolAddress((void**)&XS, g_XS);
    float* V;   cudaGetSymbolAddress((void**)&V,  g_V);

    // #1-#3: A^2, A^4, A^8
    matsq<<<NX, NX>>>(A,           PA + 0 * MS);
    matsq<<<NX, NX>>>(PA + 0 * MS, PA + 1 * MS);
    matsq<<<NX, NX>>>(PA + 1 * MS, PA + 2 * MS);

    // #4 (ncu captures launch #4): V = B u  (v1)
    {
        dim3 g(N / 32, BATCH);
        v_kernel<<<g, NX>>>(d, B, V);
    }

    // #5-#7: A^16, A^32, A^64
    matsq<<<NX, NX>>>(PA + 2 * MS, PA + 3 * MS);
    matsq<<<NX, NX>>>(PA + 3 * MS, PA + 4 * MS);
    matsq<<<NX, NX>>>(PA + 4 * MS, PA + 5 * MS);

    // #8: all M[m] = A^m B in one launch
    build_M<<<64, NX>>>(A, B);

    // #9: chunk-end contributions via GEMM
    {
        dim3 g(NCHUNK / 16, BATCH);
        gemm_wl<<<g, NX>>>(d, WL);
    }

    // #10: serial chunk combine -> start states
    pass2_combine<<<BATCH, NX>>>(PA + 5 * MS, WL, XS);

    // #11: fused sweep + y projection (prefetch depth 4)
    {
        dim3 g(NCHUNK, BATCH / 2);
        pass4_fused<<<g, NX>>>(V, A, XS, d, C, D, x, y);
    }
}